// round 16
// baseline (speedup 1.0000x reference)
#include <cuda_runtime.h>

// Problem constants: x,y are (1,1,192,192,192) f32.
#define Wd 192
#define Hd 192
#define Dd 192
#define NVOX (Wd*Hd*Dd)          // 7,077,888
#define N4   (NVOX/4)            // 1,769,472 (float4 quads)

#define RED_BLOCKS 1184
#define RED_THREADS 256

#define OUT_THREADS 256
#define HALF_BLOCKS (N4 / OUT_THREADS)    // 6912 per type
#define OUT_BLOCKS (2 * HALF_BLOCKS)      // 13824 total, types interleaved

// Scratch (no allocation allowed in kernel_launch).
__device__ float g_part[RED_BLOCKS][8];
__device__ float g_t[3];
__device__ unsigned g_count;   // zero at load; reset by last block each run

static __device__ __forceinline__ float warp_sum(float v) {
    #pragma unroll
    for (int o = 16; o > 0; o >>= 1) v += __shfl_down_sync(0xffffffffu, v, o);
    return v;
}

// ---------------------------------------------------------------------------
// Kernel 1: round-4 reduce (measured best: 14.2-14.8us; the runtime
// grid-stride loop consistently beats all exact-tiled/unrolled variants) +
// fused finalize in the last finished block.
// Per-block partial sums of 8 quantities:
//  [0]=sum x, [1]=sum x*gx, [2]=sum x*gy, [3]=sum x*gz, [4..7] same for y.
// ---------------------------------------------------------------------------
__global__ __launch_bounds__(RED_THREADS) void reduce_kernel(
    const float* __restrict__ x, const float* __restrict__ y)
{
    const float step = 2.0f / (float)(Wd - 1);
    float a[8];
    #pragma unroll
    for (int i = 0; i < 8; i++) a[i] = 0.0f;

    const float4* __restrict__ x4 = (const float4*)x;
    const float4* __restrict__ y4 = (const float4*)y;

    for (int j = blockIdx.x * blockDim.x + threadIdx.x; j < N4;
         j += gridDim.x * blockDim.x)
    {
        int e  = j * 4;                 // element index of .x
        int w  = e % Wd;                // row-aligned: all 4 in one row (192%4==0)
        int hd = e / Wd;
        int h  = hd % Hd;
        int d  = hd / Hd;

        float gx0 = fmaf((float)(w+0), step, -1.0f);
        float gx1 = fmaf((float)(w+1), step, -1.0f);
        float gx2 = fmaf((float)(w+2), step, -1.0f);
        float gx3 = fmaf((float)(w+3), step, -1.0f);
        float gy  = fmaf((float)h, step, -1.0f);
        float gz  = fmaf((float)d, step, -1.0f);

        float4 vx = __ldg(&x4[j]);
        float sx = (vx.x + vx.y) + (vx.z + vx.w);
        a[0] += sx;
        a[1] += vx.x*gx0 + vx.y*gx1 + vx.z*gx2 + vx.w*gx3;
        a[2] += sx * gy;
        a[3] += sx * gz;

        float4 vy = __ldcs(&y4[j]);
        float sy = (vy.x + vy.y) + (vy.z + vy.w);
        a[4] += sy;
        a[5] += vy.x*gx0 + vy.y*gx1 + vy.z*gx2 + vy.w*gx3;
        a[6] += sy * gy;
        a[7] += sy * gz;
    }

    __shared__ float sh[8][8];   // [warp][quantity]
    int lane = threadIdx.x & 31;
    int warp = threadIdx.x >> 5;
    #pragma unroll
    for (int q = 0; q < 8; q++) {
        float v = warp_sum(a[q]);
        if (lane == 0) sh[warp][q] = v;
    }
    __syncthreads();
    if (warp == 0) {
        #pragma unroll
        for (int q = 0; q < 8; q++) {
            float v = (lane < 8) ? sh[lane][q] : 0.0f;
            v = warp_sum(v);
            if (lane == 0) g_part[blockIdx.x][q] = v;
        }
    }

    // ---- fused finalize: last finished block reduces the partials ----
    __shared__ bool is_last;
    __threadfence();
    if (threadIdx.x == 0)
        is_last = (atomicAdd(&g_count, 1u) == (unsigned)(RED_BLOCKS - 1));
    __syncthreads();
    if (!is_last) return;
    __threadfence();

    {
        __shared__ float s[8];
        int q = warp;                   // 8 warps, one quantity each
        float acc = 0.0f;
        for (int i = lane; i < RED_BLOCKS; i += 32) acc += g_part[i][q];
        acc = warp_sum(acc);
        if (lane == 0) s[q] = acc;
        __syncthreads();
        if (threadIdx.x == 0) {
            float inv_sx = 1.0f / s[0];
            float inv_sy = 1.0f / s[4];
            g_t[0] = s[1] * inv_sx - s[5] * inv_sy;
            g_t[1] = s[2] * inv_sx - s[6] * inv_sy;
            g_t[2] = s[3] * inv_sx - s[7] * inv_sy;
            g_count = 0;                // reset for next graph replay
        }
    }
}

// ---------------------------------------------------------------------------
// Kernel 2: heterogeneous output kernel. Even blocks run the transform path
// (round-8 sampler minus the grid stores — exact same tap arithmetic); odd
// blocks run the grid-writer path (pure streaming stores, exact same grid
// expressions). Interleaving block types in one launch lets the SM scheduler
// fill the transform warps' load-stall issue slots with the writers' stores.
// ---------------------------------------------------------------------------
__global__ __launch_bounds__(OUT_THREADS, 6) void output_kernel(
    const float* __restrict__ vol,
    float* __restrict__ out_t,      // NVOX floats
    float* __restrict__ out_g)      // NVOX*3 floats
{
    int type = blockIdx.x & 1;
    int b    = blockIdx.x >> 1;
    int j    = b * OUT_THREADS + threadIdx.x;   // exact tiling, no guard

    const float step = 2.0f / (float)(Wd - 1);
    const float tx = g_t[0], ty = g_t[1], tz = g_t[2];

    int e  = j * 4;
    int w0 = e % Wd;
    int hd = e / Wd;
    int h  = hd % Hd;
    int d  = hd / Hd;

    float gy = fmaf((float)h, step, -1.0f);
    float gz = fmaf((float)d, step, -1.0f);
    float goy = gy + ty;
    float goz = gz + tz;

    // Per-voxel x grid coords (same expressions in both paths).
    float gox0 = fmaf((float)(w0+0), step, -1.0f) + tx;
    float gox1 = fmaf((float)(w0+1), step, -1.0f) + tx;
    float gox2 = fmaf((float)(w0+2), step, -1.0f) + tx;
    float gox3 = fmaf((float)(w0+3), step, -1.0f) + tx;

    if (type == 1) {
        // ---- grid-writer path: pure streaming stores ----
        float4* g4 = (float4*)(out_g + (long)e * 3);   // e*3 = j*12, 16B-aligned
        __stcs(g4 + 0, make_float4(gox0, goy, goz, gox1));
        __stcs(g4 + 1, make_float4(goy, goz, gox2, goy));
        __stcs(g4 + 2, make_float4(goz, gox3, goy, goz));
        return;
    }

    // ---- transform path (round-8 sampler, grid stores removed) ----
    float iy = (goy + 1.0f) * 0.5f * (float)(Hd - 1);
    float iz = (goz + 1.0f) * 0.5f * (float)(Dd - 1);
    float iy0f = floorf(iy), iz0f = floorf(iz);
    float wy = iy - iy0f,    wz = iz - iz0f;
    int iy0 = (int)iy0f, iz0 = (int)iz0f;
    int iy1 = iy0 + 1,   iz1 = iz0 + 1;

    float vy0 = (iy0 >= 0 && iy0 < Hd) ? 1.0f : 0.0f;
    float vy1 = (iy1 >= 0 && iy1 < Hd) ? 1.0f : 0.0f;
    float vz0 = (iz0 >= 0 && iz0 < Dd) ? 1.0f : 0.0f;
    float vz1 = (iz1 >= 0 && iz1 < Dd) ? 1.0f : 0.0f;
    int cy0 = min(max(iy0, 0), Hd - 1);
    int cy1 = min(max(iy1, 0), Hd - 1);
    int cz0 = min(max(iz0, 0), Dd - 1);
    int cz1 = min(max(iz1, 0), Dd - 1);

    int rb[4];
    rb[0] = cz0 * (Hd * Wd) + cy0 * Wd;   // b00
    rb[1] = cz0 * (Hd * Wd) + cy1 * Wd;   // b01
    rb[2] = cz1 * (Hd * Wd) + cy0 * Wd;   // b10
    rb[3] = cz1 * (Hd * Wd) + cy1 * Wd;   // b11

    float qq[4];
    qq[0] = (1.0f - wz) * (1.0f - wy) * vz0 * vy0;
    qq[1] = (1.0f - wz) * wy          * vz0 * vy1;
    qq[2] = wz          * (1.0f - wy) * vz1 * vy0;
    qq[3] = wz          * wy          * vz1 * vy1;

    float wxa[4], wxb[4];
    int   cx0a[4], cx1a[4];
    float goxv[4] = {gox0, gox1, gox2, gox3};
    #pragma unroll
    for (int k = 0; k < 4; k++) {
        float ix = (goxv[k] + 1.0f) * 0.5f * (float)(Wd - 1);
        float ix0f = floorf(ix);
        float wx = ix - ix0f;
        int ix0 = (int)ix0f;
        int ix1 = ix0 + 1;
        float vx0 = (ix0 >= 0 && ix0 < Wd) ? 1.0f : 0.0f;
        float vx1 = (ix1 >= 0 && ix1 < Wd) ? 1.0f : 0.0f;
        cx0a[k] = min(max(ix0, 0), Wd - 1);
        cx1a[k] = min(max(ix1, 0), Wd - 1);
        wxa[k] = (1.0f - wx) * vx0;
        wxb[k] = wx * vx1;
    }

    int ce3 = min(w0 + 4, Wd - 1);   // expected clamped cx1 for k=3, shift 0
    int cm0 = max(w0 - 1, 0);        // expected clamped cx0 for k=0, shift -1

    bool f0 = (cx0a[0]==w0)   & (cx0a[1]==w0+1) & (cx0a[2]==w0+2) & (cx0a[3]==w0+3)
            & (cx1a[0]==w0+1) & (cx1a[1]==w0+2) & (cx1a[2]==w0+3) & (cx1a[3]==ce3);
    bool fm = (cx0a[0]==cm0)  & (cx0a[1]==w0)   & (cx0a[2]==w0+1) & (cx0a[3]==w0+2)
            & (cx1a[0]==w0)   & (cx1a[1]==w0+1) & (cx1a[2]==w0+2) & (cx1a[3]==w0+3);

    float tr[4] = {0.0f, 0.0f, 0.0f, 0.0f};

    if (f0) {
        // window: A = vol[rb + w0 .. w0+3], R = vol[rb + ce3]
        float4 A[4]; float Rs[4];
        #pragma unroll
        for (int r = 0; r < 4; r++) {
            A[r]  = __ldg((const float4*)(vol + rb[r] + w0));
            Rs[r] = __ldg(vol + rb[r] + ce3);
        }
        #pragma unroll
        for (int r = 0; r < 4; r++) {
            tr[0] += qq[r] * (A[r].x * wxa[0] + A[r].y * wxb[0]);
            tr[1] += qq[r] * (A[r].y * wxa[1] + A[r].z * wxb[1]);
            tr[2] += qq[r] * (A[r].z * wxa[2] + A[r].w * wxb[2]);
            tr[3] += qq[r] * (A[r].w * wxa[3] + Rs[r]  * wxb[3]);
        }
    } else if (fm) {
        // window: L = vol[rb + cm0], A = vol[rb + w0 .. w0+3]
        float4 A[4]; float Ls[4];
        #pragma unroll
        for (int r = 0; r < 4; r++) {
            A[r]  = __ldg((const float4*)(vol + rb[r] + w0));
            Ls[r] = __ldg(vol + rb[r] + cm0);
        }
        #pragma unroll
        for (int r = 0; r < 4; r++) {
            tr[0] += qq[r] * (Ls[r]  * wxa[0] + A[r].x * wxb[0]);
            tr[1] += qq[r] * (A[r].x * wxa[1] + A[r].y * wxb[1]);
            tr[2] += qq[r] * (A[r].y * wxa[2] + A[r].z * wxb[2]);
            tr[3] += qq[r] * (A[r].z * wxa[3] + A[r].w * wxb[3]);
        }
    } else {
        // General fallback: exact scalar gathers (rare rounding flips).
        #pragma unroll
        for (int k = 0; k < 4; k++) {
            int cx0 = cx0a[k], cx1 = cx1a[k];
            #pragma unroll
            for (int r = 0; r < 4; r++) {
                float v = __ldg(&vol[rb[r] + cx0]) * wxa[k]
                        + __ldg(&vol[rb[r] + cx1]) * wxb[k];
                tr[k] += qq[r] * v;
            }
        }
    }

    // Streaming store (output never re-read; keep x resident in L2).
    __stcs(((float4*)out_t) + j, make_float4(tr[0], tr[1], tr[2], tr[3]));
}

// ---------------------------------------------------------------------------
extern "C" void kernel_launch(void* const* d_in, const int* in_sizes, int n_in,
                              void* d_out, int out_size)
{
    const float* x = (const float*)d_in[0];
    const float* y = (const float*)d_in[1];
    float* out_transformed = (float*)d_out;            // NVOX floats
    float* out_grid        = (float*)d_out + NVOX;     // NVOX*3 floats

    reduce_kernel<<<RED_BLOCKS, RED_THREADS>>>(x, y);
    output_kernel<<<OUT_BLOCKS, OUT_THREADS>>>(x, out_transformed, out_grid);
}

// round 17
// speedup vs baseline: 1.0651x; 1.0651x over previous
#include <cuda_runtime.h>

// Problem constants: x,y are (1,1,192,192,192) f32.
#define Wd 192
#define Hd 192
#define Dd 192
#define NVOX (Wd*Hd*Dd)          // 7,077,888
#define N4   (NVOX/4)            // 1,769,472 (float4 quads)

#define RED_BLOCKS 1184
#define RED_THREADS 256

#define SAMP_THREADS 128
#define SAMP_BLOCKS (N4 / SAMP_THREADS)   // 13824 exactly

// Scratch (no allocation allowed in kernel_launch).
__device__ float g_part[RED_BLOCKS][8];
__device__ float g_t[3];
__device__ unsigned g_count;   // zero at load; reset by last block each run

static __device__ __forceinline__ float warp_sum(float v) {
    #pragma unroll
    for (int o = 16; o > 0; o >>= 1) v += __shfl_down_sync(0xffffffffu, v, o);
    return v;
}

// ---------------------------------------------------------------------------
// Kernel 1: round-4 reduce (measured best: 14.2-14.8us; the runtime
// grid-stride loop consistently beats all exact-tiled/unrolled variants) +
// fused finalize in the last finished block.
// Per-block partial sums of 8 quantities:
//  [0]=sum x, [1]=sum x*gx, [2]=sum x*gy, [3]=sum x*gz, [4..7] same for y.
// ---------------------------------------------------------------------------
__global__ __launch_bounds__(RED_THREADS) void reduce_kernel(
    const float* __restrict__ x, const float* __restrict__ y)
{
    const float step = 2.0f / (float)(Wd - 1);
    float a[8];
    #pragma unroll
    for (int i = 0; i < 8; i++) a[i] = 0.0f;

    const float4* __restrict__ x4 = (const float4*)x;
    const float4* __restrict__ y4 = (const float4*)y;

    for (int j = blockIdx.x * blockDim.x + threadIdx.x; j < N4;
         j += gridDim.x * blockDim.x)
    {
        int e  = j * 4;                 // element index of .x
        int w  = e % Wd;                // row-aligned: all 4 in one row (192%4==0)
        int hd = e / Wd;
        int h  = hd % Hd;
        int d  = hd / Hd;

        float gx0 = fmaf((float)(w+0), step, -1.0f);
        float gx1 = fmaf((float)(w+1), step, -1.0f);
        float gx2 = fmaf((float)(w+2), step, -1.0f);
        float gx3 = fmaf((float)(w+3), step, -1.0f);
        float gy  = fmaf((float)h, step, -1.0f);
        float gz  = fmaf((float)d, step, -1.0f);

        float4 vx = __ldg(&x4[j]);
        float sx = (vx.x + vx.y) + (vx.z + vx.w);
        a[0] += sx;
        a[1] += vx.x*gx0 + vx.y*gx1 + vx.z*gx2 + vx.w*gx3;
        a[2] += sx * gy;
        a[3] += sx * gz;

        float4 vy = __ldcs(&y4[j]);
        float sy = (vy.x + vy.y) + (vy.z + vy.w);
        a[4] += sy;
        a[5] += vy.x*gx0 + vy.y*gx1 + vy.z*gx2 + vy.w*gx3;
        a[6] += sy * gy;
        a[7] += sy * gz;
    }

    __shared__ float sh[8][8];   // [warp][quantity]
    int lane = threadIdx.x & 31;
    int warp = threadIdx.x >> 5;
    #pragma unroll
    for (int q = 0; q < 8; q++) {
        float v = warp_sum(a[q]);
        if (lane == 0) sh[warp][q] = v;
    }
    __syncthreads();
    if (warp == 0) {
        #pragma unroll
        for (int q = 0; q < 8; q++) {
            float v = (lane < 8) ? sh[lane][q] : 0.0f;
            v = warp_sum(v);
            if (lane == 0) g_part[blockIdx.x][q] = v;
        }
    }

    // ---- fused finalize: last finished block reduces the partials ----
    __shared__ bool is_last;
    __threadfence();
    if (threadIdx.x == 0)
        is_last = (atomicAdd(&g_count, 1u) == (unsigned)(RED_BLOCKS - 1));
    __syncthreads();
    if (!is_last) return;
    __threadfence();

    {
        __shared__ float s[8];
        int q = warp;                   // 8 warps, one quantity each
        float acc = 0.0f;
        for (int i = lane; i < RED_BLOCKS; i += 32) acc += g_part[i][q];
        acc = warp_sum(acc);
        if (lane == 0) s[q] = acc;
        __syncthreads();
        if (threadIdx.x == 0) {
            float inv_sx = 1.0f / s[0];
            float inv_sy = 1.0f / s[4];
            g_t[0] = s[1] * inv_sx - s[5] * inv_sy;
            g_t[1] = s[2] * inv_sx - s[6] * inv_sy;
            g_t[2] = s[3] * inv_sx - s[7] * inv_sy;
            g_count = 0;                // reset for next graph replay
        }
    }
}

// ---------------------------------------------------------------------------
// Kernel 2 (round-8/15 code verbatim; only blockDim changed to 128): grid =
// base+t and transformed = trilinear(x, grid). 4 voxels (along w) per thread;
// one aligned float4 + one scalar per corner row (8 LDGs/thread). Fast paths
// validated against the exactly-computed per-voxel indices -> bitwise
// identical to the scalar path.
// ---------------------------------------------------------------------------
__global__ __launch_bounds__(SAMP_THREADS, 12) void sample_kernel(
    const float* __restrict__ vol,
    float* __restrict__ out_t,      // NVOX floats
    float* __restrict__ out_g)      // NVOX*3 floats
{
    int j = blockIdx.x * SAMP_THREADS + threadIdx.x;   // exact tiling, no guard

    const float step = 2.0f / (float)(Wd - 1);
    const float tx = g_t[0], ty = g_t[1], tz = g_t[2];

    int e  = j * 4;
    int w0 = e % Wd;
    int hd = e / Wd;
    int h  = hd % Hd;
    int d  = hd / Hd;

    float gy = fmaf((float)h, step, -1.0f);
    float gz = fmaf((float)d, step, -1.0f);
    float goy = gy + ty;
    float goz = gz + tz;

    // Per-voxel x grid coords (also the grid output x-channel).
    float gox0 = fmaf((float)(w0+0), step, -1.0f) + tx;
    float gox1 = fmaf((float)(w0+1), step, -1.0f) + tx;
    float gox2 = fmaf((float)(w0+2), step, -1.0f) + tx;
    float gox3 = fmaf((float)(w0+3), step, -1.0f) + tx;

    // Early streaming grid stores (depend only on coords + t; frees registers
    // and overlaps with the volume loads below).
    {
        float4* g4 = (float4*)(out_g + (long)e * 3);   // e*3 = j*12, 16B-aligned
        __stcs(g4 + 0, make_float4(gox0, goy, goz, gox1));
        __stcs(g4 + 1, make_float4(goy, goz, gox2, goy));
        __stcs(g4 + 2, make_float4(goz, gox3, goy, goz));
    }

    // y/z sample coords shared by all 4 voxels.
    float iy = (goy + 1.0f) * 0.5f * (float)(Hd - 1);
    float iz = (goz + 1.0f) * 0.5f * (float)(Dd - 1);
    float iy0f = floorf(iy), iz0f = floorf(iz);
    float wy = iy - iy0f,    wz = iz - iz0f;
    int iy0 = (int)iy0f, iz0 = (int)iz0f;
    int iy1 = iy0 + 1,   iz1 = iz0 + 1;

    float vy0 = (iy0 >= 0 && iy0 < Hd) ? 1.0f : 0.0f;
    float vy1 = (iy1 >= 0 && iy1 < Hd) ? 1.0f : 0.0f;
    float vz0 = (iz0 >= 0 && iz0 < Dd) ? 1.0f : 0.0f;
    float vz1 = (iz1 >= 0 && iz1 < Dd) ? 1.0f : 0.0f;
    int cy0 = min(max(iy0, 0), Hd - 1);
    int cy1 = min(max(iy1, 0), Hd - 1);
    int cz0 = min(max(iz0, 0), Dd - 1);
    int cz1 = min(max(iz1, 0), Dd - 1);

    int rb[4];   // fits easily in 32 bits (max ~7M)
    rb[0] = cz0 * (Hd * Wd) + cy0 * Wd;   // b00
    rb[1] = cz0 * (Hd * Wd) + cy1 * Wd;   // b01
    rb[2] = cz1 * (Hd * Wd) + cy0 * Wd;   // b10
    rb[3] = cz1 * (Hd * Wd) + cy1 * Wd;   // b11

    float qq[4];
    qq[0] = (1.0f - wz) * (1.0f - wy) * vz0 * vy0;
    qq[1] = (1.0f - wz) * wy          * vz0 * vy1;
    qq[2] = wz          * (1.0f - wy) * vz1 * vy0;
    qq[3] = wz          * wy          * vz1 * vy1;

    // Per-voxel x coordinates (exact, same arithmetic as the reference path).
    float wxa[4], wxb[4];
    int   cx0a[4], cx1a[4];
    float goxv[4] = {gox0, gox1, gox2, gox3};
    #pragma unroll
    for (int k = 0; k < 4; k++) {
        float ix = (goxv[k] + 1.0f) * 0.5f * (float)(Wd - 1);
        float ix0f = floorf(ix);
        float wx = ix - ix0f;
        int ix0 = (int)ix0f;
        int ix1 = ix0 + 1;
        float vx0 = (ix0 >= 0 && ix0 < Wd) ? 1.0f : 0.0f;
        float vx1 = (ix1 >= 0 && ix1 < Wd) ? 1.0f : 0.0f;
        cx0a[k] = min(max(ix0, 0), Wd - 1);
        cx1a[k] = min(max(ix1, 0), Wd - 1);
        wxa[k] = (1.0f - wx) * vx0;
        wxb[k] = wx * vx1;
    }

    int ce3 = min(w0 + 4, Wd - 1);   // expected clamped cx1 for k=3, shift 0
    int cm0 = max(w0 - 1, 0);        // expected clamped cx0 for k=0, shift -1

    bool f0 = (cx0a[0]==w0)   & (cx0a[1]==w0+1) & (cx0a[2]==w0+2) & (cx0a[3]==w0+3)
            & (cx1a[0]==w0+1) & (cx1a[1]==w0+2) & (cx1a[2]==w0+3) & (cx1a[3]==ce3);
    bool fm = (cx0a[0]==cm0)  & (cx0a[1]==w0)   & (cx0a[2]==w0+1) & (cx0a[3]==w0+2)
            & (cx1a[0]==w0)   & (cx1a[1]==w0+1) & (cx1a[2]==w0+2) & (cx1a[3]==w0+3);

    float tr[4] = {0.0f, 0.0f, 0.0f, 0.0f};

    if (f0) {
        // window: A = vol[rb + w0 .. w0+3], R = vol[rb + ce3]
        float4 A[4]; float Rs[4];
        #pragma unroll
        for (int r = 0; r < 4; r++) {
            A[r]  = __ldg((const float4*)(vol + rb[r] + w0));
            Rs[r] = __ldg(vol + rb[r] + ce3);
        }
        #pragma unroll
        for (int r = 0; r < 4; r++) {
            tr[0] += qq[r] * (A[r].x * wxa[0] + A[r].y * wxb[0]);
            tr[1] += qq[r] * (A[r].y * wxa[1] + A[r].z * wxb[1]);
            tr[2] += qq[r] * (A[r].z * wxa[2] + A[r].w * wxb[2]);
            tr[3] += qq[r] * (A[r].w * wxa[3] + Rs[r]  * wxb[3]);
        }
    } else if (fm) {
        // window: L = vol[rb + cm0], A = vol[rb + w0 .. w0+3]
        float4 A[4]; float Ls[4];
        #pragma unroll
        for (int r = 0; r < 4; r++) {
            A[r]  = __ldg((const float4*)(vol + rb[r] + w0));
            Ls[r] = __ldg(vol + rb[r] + cm0);
        }
        #pragma unroll
        for (int r = 0; r < 4; r++) {
            tr[0] += qq[r] * (Ls[r]  * wxa[0] + A[r].x * wxb[0]);
            tr[1] += qq[r] * (A[r].x * wxa[1] + A[r].y * wxb[1]);
            tr[2] += qq[r] * (A[r].y * wxa[2] + A[r].z * wxb[2]);
            tr[3] += qq[r] * (A[r].z * wxa[3] + A[r].w * wxb[3]);
        }
    } else {
        // General fallback: exact scalar gathers (rare: |shift| >= 1 or
        // inconsistent rounding flips).
        #pragma unroll
        for (int k = 0; k < 4; k++) {
            int cx0 = cx0a[k], cx1 = cx1a[k];
            #pragma unroll
            for (int r = 0; r < 4; r++) {
                float v = __ldg(&vol[rb[r] + cx0]) * wxa[k]
                        + __ldg(&vol[rb[r] + cx1]) * wxb[k];
                tr[k] += qq[r] * v;
            }
        }
    }

    // Streaming store (output never re-read; keep x resident in L2).
    __stcs(((float4*)out_t) + j, make_float4(tr[0], tr[1], tr[2], tr[3]));
}

// ---------------------------------------------------------------------------
extern "C" void kernel_launch(void* const* d_in, const int* in_sizes, int n_in,
                              void* d_out, int out_size)
{
    const float* x = (const float*)d_in[0];
    const float* y = (const float*)d_in[1];
    float* out_transformed = (float*)d_out;            // NVOX floats
    float* out_grid        = (float*)d_out + NVOX;     // NVOX*3 floats

    reduce_kernel<<<RED_BLOCKS, RED_THREADS>>>(x, y);
    sample_kernel<<<SAMP_BLOCKS, SAMP_THREADS>>>(x, out_transformed, out_grid);
}